// round 7
// baseline (speedup 1.0000x reference)
#include <cuda_runtime.h>
#include <cstdint>

// Problem constants (shapes fixed by the reference: x [8,8192,128], embed [1024,128])
#define DIM     128
#define KCODES  1024
#define ROWS    64      // x rows per block
#define CT      64      // codes per tile
#define STRIDE4 33      // padded row stride in float4 (132 floats) -> conflict-free LDS

static const float DECAY_F = 0.99f;
static const float OMD_F   = (float)(1.0 - 0.99);   // matches python 1.0 - decay cast to f32
static const float EPS_F   = 1e-5f;

// Scratch (no cudaMalloc allowed): device globals
__device__ float g_counts[KCODES];
__device__ float g_sums[KCODES * DIM];
__device__ float g_enorm[KCODES];
__device__ float g_inv[KCODES];

// ---------------------------------------------------------------------------
// packed fp32x2 FMA (Blackwell FFMA2): d = a*b + d elementwise on 2 packed f32
// ---------------------------------------------------------------------------
__device__ __forceinline__ void ffma2(unsigned long long& d,
                                      unsigned long long a,
                                      unsigned long long b) {
    asm("fma.rn.f32x2 %0, %1, %2, %0;" : "+l"(d) : "l"(a), "l"(b));
}

// ---------------------------------------------------------------------------
// Kernel 0: per-code squared norms + zero the accumulation scratch
// grid = KCODES blocks x DIM threads
// ---------------------------------------------------------------------------
__global__ void k_init(const float* __restrict__ embed) {
    int k = blockIdx.x;
    int t = threadIdx.x;
    float v = embed[k * DIM + t];
    float p = v * v;
#pragma unroll
    for (int off = 16; off > 0; off >>= 1)
        p += __shfl_down_sync(0xffffffffu, p, off);
    __shared__ float s[4];
    if ((t & 31) == 0) s[t >> 5] = p;
    __syncthreads();
    if (t == 0) {
        g_enorm[k]  = s[0] + s[1] + s[2] + s[3];
        g_counts[k] = 0.0f;
    }
    g_sums[(size_t)k * DIM + t] = 0.0f;
}

// ---------------------------------------------------------------------------
// Kernel 1: fused distance-GEMM + argmax + quantize gather + segment-sum scatter
// grid = N/ROWS blocks x 256 threads
// Thread map: ty = tid/16 (row group), tx = tid%16 (code group)
//   rows  owned by thread: ty + i*16, i in 0..3
//   codes owned per tile : tx + j*16, j in 0..3
// ---------------------------------------------------------------------------
__global__ __launch_bounds__(256) void k_main(const float* __restrict__ x,
                                              const float* __restrict__ embed,
                                              float* __restrict__ out,
                                              long long indOff) {
    extern __shared__ unsigned char sm[];
    ulonglong2 (*xs)[STRIDE4] = (ulonglong2(*)[STRIDE4])sm;
    ulonglong2 (*es)[STRIDE4] = (ulonglong2(*)[STRIDE4])(sm + (size_t)ROWS * STRIDE4 * 16);
    float* enorm_s = (float*)(sm + 2 * (size_t)ROWS * STRIDE4 * 16);
    int*   best_s  = (int*)(enorm_s + CT);

    const int tid = threadIdx.x;
    const int tx  = tid & 15;
    const int ty  = tid >> 4;
    const long long rowBase = (long long)blockIdx.x * ROWS;

    // Load x tile [64][128] (coalesced float4)
    const float4* xg = (const float4*)(x + rowBase * DIM);
#pragma unroll
    for (int m = 0; m < 8; m++) {
        int flat = tid + m * 256;
        int r = flat >> 5, c = flat & 31;
        ((float4*)&xs[r][c])[0] = xg[r * 32 + c];
    }

    float bestScore[4];
    int   bestIdx[4];
#pragma unroll
    for (int i = 0; i < 4; i++) { bestScore[i] = -3.4e38f; bestIdx[i] = 0; }

    for (int tile = 0; tile < KCODES / CT; tile++) {
        __syncthreads();   // protect es/enorm_s reuse from previous iteration
        const float4* eg = (const float4*)(embed + (size_t)tile * CT * DIM);
#pragma unroll
        for (int m = 0; m < 8; m++) {
            int flat = tid + m * 256;
            int r = flat >> 5, c = flat & 31;
            ((float4*)&es[r][c])[0] = eg[r * 32 + c];
        }
        if (tid < CT) enorm_s[tid] = g_enorm[tile * CT + tid];
        __syncthreads();

        unsigned long long acc[4][4];
#pragma unroll
        for (int i = 0; i < 4; i++)
#pragma unroll
            for (int j = 0; j < 4; j++) acc[i][j] = 0ull;

#pragma unroll 8
        for (int k4 = 0; k4 < 32; k4++) {
            ulonglong2 a[4], b[4];
#pragma unroll
            for (int i = 0; i < 4; i++) a[i] = xs[ty + i * 16][k4];
#pragma unroll
            for (int j = 0; j < 4; j++) b[j] = es[tx + j * 16][k4];
#pragma unroll
            for (int i = 0; i < 4; i++)
#pragma unroll
                for (int j = 0; j < 4; j++) {
                    ffma2(acc[i][j], a[i].x, b[j].x);
                    ffma2(acc[i][j], a[i].y, b[j].y);
                }
        }

        // score = 2*dot - ||e||^2 ; argmax with first-index tie-break
#pragma unroll
        for (int i = 0; i < 4; i++)
#pragma unroll
            for (int j = 0; j < 4; j++) {
                unsigned long long v = acc[i][j];
                float lo  = __uint_as_float((unsigned)v);
                float hi  = __uint_as_float((unsigned)(v >> 32));
                float dot = lo + hi;
                int   code = tile * CT + j * 16 + tx;
                float sc   = 2.0f * dot - enorm_s[j * 16 + tx];
                if (sc > bestScore[i] || (sc == bestScore[i] && code < bestIdx[i])) {
                    bestScore[i] = sc;
                    bestIdx[i]   = code;
                }
            }
    }

    // Reduce over tx (16 contiguous lanes = half warp)
#pragma unroll
    for (int i = 0; i < 4; i++) {
        float s = bestScore[i];
        int   idx = bestIdx[i];
#pragma unroll
        for (int off = 8; off > 0; off >>= 1) {
            float so = __shfl_down_sync(0xffffffffu, s, off, 16);
            int   io = __shfl_down_sync(0xffffffffu, idx, off, 16);
            if (so > s || (so == s && io < idx)) { s = so; idx = io; }
        }
        if (tx == 0) best_s[ty + i * 16] = idx;
    }
    __syncthreads();

    // Epilogue: quantize rows (gather embed[best]) + segment-sum scatter (atomics)
#pragma unroll
    for (int m = 0; m < 8; m++) {
        int flat = tid + m * 256;
        int r = flat >> 5, c = flat & 31;
        int best = best_s[r];
        float4 e4 = ((const float4*)(embed + (size_t)best * DIM))[c];
        ((float4*)(out + (rowBase + r) * DIM))[c] = e4;
        float4 xv = ((float4*)&xs[r][c])[0];
        float* sp = g_sums + (size_t)best * DIM + c * 4;
        atomicAdd(sp + 0, xv.x);
        atomicAdd(sp + 1, xv.y);
        atomicAdd(sp + 2, xv.z);
        atomicAdd(sp + 3, xv.w);
    }
    if (tid < ROWS) {
        int best = best_s[tid];
        atomicAdd(&g_counts[best], 1.0f);
        out[indOff + rowBase + tid] = (float)best;
    }
}

// ---------------------------------------------------------------------------
// Kernel 2a: new_cluster_size + total + 1/smoothed_counts   (1 block, 1024 thr)
// ---------------------------------------------------------------------------
__global__ void k_final1(const float* __restrict__ cs,
                         float* __restrict__ out,
                         long long ncsOff) {
    __shared__ float red[KCODES];
    int k = threadIdx.x;
    float ncs = cs[k] * DECAY_F + OMD_F * g_counts[k];
    out[ncsOff + k] = ncs;
    red[k] = ncs;
    __syncthreads();
    for (int s = KCODES / 2; s > 0; s >>= 1) {
        if (k < s) red[k] += red[k + s];
        __syncthreads();
    }
    float total    = red[0];
    float smoothed = (ncs + EPS_F) / (total + (float)KCODES * EPS_F);
    g_inv[k] = 1.0f / (smoothed * total);
}

// ---------------------------------------------------------------------------
// Kernel 2b: new_embed_avg + new_embed (131072 elems)
// ---------------------------------------------------------------------------
__global__ void k_final2(const float* __restrict__ ea,
                         float* __restrict__ out,
                         long long neaOff, long long neOff) {
    int i = blockIdx.x * blockDim.x + threadIdx.x;
    float nea = ea[i] * DECAY_F + OMD_F * g_sums[i];
    out[neaOff + i] = nea;
    out[neOff + i]  = nea * g_inv[i >> 7];
}

// ---------------------------------------------------------------------------
extern "C" void kernel_launch(void* const* d_in, const int* in_sizes, int n_in,
                              void* d_out, int out_size) {
    const float* x     = (const float*)d_in[0];
    const float* embed = (const float*)d_in[1];
    const float* cs    = (const float*)d_in[2];
    const float* ea    = (const float*)d_in[3];
    float* out = (float*)d_out;

    const long long N = in_sizes[0] / DIM;   // 65536 rows
    const long long indOff = N * DIM;                 // quantize size
    const long long ncsOff = indOff + N;              // + embed_ind
    const long long neaOff = ncsOff + KCODES;         // + new_cluster_size
    const long long neOff  = neaOff + (long long)KCODES * DIM;

    static bool attr_set = false;
    const int SMEM_SZ = 2 * ROWS * STRIDE4 * 16 + CT * 4 + ROWS * 4;
    if (!attr_set) {
        cudaFuncSetAttribute(k_main, cudaFuncAttributeMaxDynamicSharedMemorySize, SMEM_SZ);
        attr_set = true;
    }

    k_init<<<KCODES, DIM>>>(embed);
    k_main<<<(unsigned)(N / ROWS), 256, SMEM_SZ>>>(x, embed, out, indOff);
    k_final1<<<1, KCODES>>>(cs, out, ncsOff);
    k_final2<<<KCODES * DIM / 256, 256>>>(ea, out, neaOff, neOff);
}

// round 8
// speedup vs baseline: 1.0285x; 1.0285x over previous
#include <cuda_runtime.h>
#include <cstdint>

// Problem constants (shapes fixed by the reference: x [8,8192,128], embed [1024,128])
#define DIM     128
#define KCODES  1024
#define ROWS    64      // x rows per block
#define CT      128     // codes per tile (8 tiles)
#define STRIDE4 33      // padded row stride in float4 (132 floats)

static const float DECAY_F = 0.99f;
static const float OMD_F   = (float)(1.0 - 0.99);
static const float EPS_F   = 1e-5f;

// Scratch (no cudaMalloc allowed): device globals
__device__ float g_counts[KCODES];
__device__ float g_sums[KCODES * DIM];
__device__ float g_enorm[KCODES];
__device__ float g_inv[KCODES];

// packed fp32x2 FMA (Blackwell FFMA2): d = a*b + d on 2 packed f32
__device__ __forceinline__ void ffma2(unsigned long long& d,
                                      unsigned long long a,
                                      unsigned long long b) {
    asm("fma.rn.f32x2 %0, %1, %2, %0;" : "+l"(d) : "l"(a), "l"(b));
}

// ---------------------------------------------------------------------------
// Kernel 0: per-code squared norms + zero the accumulation scratch
// ---------------------------------------------------------------------------
__global__ void k_init(const float* __restrict__ embed) {
    int k = blockIdx.x;
    int t = threadIdx.x;
    float v = embed[k * DIM + t];
    float p = v * v;
#pragma unroll
    for (int off = 16; off > 0; off >>= 1)
        p += __shfl_down_sync(0xffffffffu, p, off);
    __shared__ float s[4];
    if ((t & 31) == 0) s[t >> 5] = p;
    __syncthreads();
    if (t == 0) {
        g_enorm[k]  = s[0] + s[1] + s[2] + s[3];
        g_counts[k] = 0.0f;
    }
    g_sums[(size_t)k * DIM + t] = 0.0f;
}

// ---------------------------------------------------------------------------
// Kernel 1: fused distance-GEMM + argmax + quantize gather + segment-sum
// grid = N/64 blocks x 128 threads (4 warps). 2 blocks/SM (102 KB smem each).
// Thread map: tx = tid&15 (code groups), ty = tid>>4 (row groups, 0..7)
//   rows  owned: ty + i*8,  i = 0..7   (64 rows/block)
//   codes owned: tx + j*16, j = 0..7   (128 codes/tile)
// 8x8 f32x2 microtile: 256 B smem -> 256 FMA per k4 step (1.0 B/FMA).
// ---------------------------------------------------------------------------
__global__ __launch_bounds__(128) void k_main(const float* __restrict__ x,
                                              const float* __restrict__ embed,
                                              float* __restrict__ out,
                                              long long indOff) {
    extern __shared__ unsigned char sm[];
    ulonglong2 (*xs)[STRIDE4] = (ulonglong2(*)[STRIDE4])sm;
    ulonglong2 (*es)[STRIDE4] = (ulonglong2(*)[STRIDE4])(sm + (size_t)ROWS * STRIDE4 * 16);
    float* enorm_s = (float*)(sm + (size_t)(ROWS + CT) * STRIDE4 * 16);
    int*   best_s  = (int*)(enorm_s + CT);

    const int tid = threadIdx.x;
    const int tx  = tid & 15;
    const int ty  = tid >> 4;
    const long long rowBase = (long long)blockIdx.x * ROWS;

    // Load x tile [64][128] (coalesced float4): 2048 float4 / 128 thr = 16 ea
    const float4* xg = (const float4*)(x + rowBase * DIM);
#pragma unroll
    for (int m = 0; m < 16; m++) {
        int flat = tid + m * 128;
        int r = flat >> 5, c = flat & 31;
        ((float4*)xs[r])[c] = xg[flat];
    }

    float bestScore[8];
    int   bestIdx[8];
#pragma unroll
    for (int i = 0; i < 8; i++) { bestScore[i] = -3.4e38f; bestIdx[i] = 0; }

    for (int tile = 0; tile < KCODES / CT; tile++) {
        __syncthreads();   // protect es/enorm_s reuse from previous iteration
        const float4* eg = (const float4*)(embed + (size_t)tile * CT * DIM);
#pragma unroll
        for (int m = 0; m < 32; m++) {
            int flat = tid + m * 128;
            int r = flat >> 5, c = flat & 31;
            ((float4*)es[r])[c] = eg[flat];
        }
        enorm_s[tid] = g_enorm[tile * CT + tid];
        __syncthreads();

        unsigned long long acc[8][8];
#pragma unroll
        for (int i = 0; i < 8; i++)
#pragma unroll
            for (int j = 0; j < 8; j++) acc[i][j] = 0ull;

#pragma unroll 1
        for (int k4 = 0; k4 < 32; k4++) {
            ulonglong2 a[8], b[8];
#pragma unroll
            for (int i = 0; i < 8; i++) a[i] = xs[ty + i * 8][k4];
#pragma unroll
            for (int j = 0; j < 8; j++) b[j] = es[tx + j * 16][k4];
#pragma unroll
            for (int i = 0; i < 8; i++)
#pragma unroll
                for (int j = 0; j < 8; j++) {
                    ffma2(acc[i][j], a[i].x, b[j].x);
                    ffma2(acc[i][j], a[i].y, b[j].y);
                }
        }

        // score = 2*dot - ||e||^2 ; argmax, first-index tie-break
#pragma unroll
        for (int i = 0; i < 8; i++)
#pragma unroll
            for (int j = 0; j < 8; j++) {
                unsigned long long v = acc[i][j];
                float lo  = __uint_as_float((unsigned)v);
                float hi  = __uint_as_float((unsigned)(v >> 32));
                float dot = lo + hi;
                int   code = tile * CT + j * 16 + tx;
                float sc   = 2.0f * dot - enorm_s[j * 16 + tx];
                if (sc > bestScore[i] || (sc == bestScore[i] && code < bestIdx[i])) {
                    bestScore[i] = sc;
                    bestIdx[i]   = code;
                }
            }
    }

    // Reduce over the 16 tx lanes (half-warp, width 16)
#pragma unroll
    for (int i = 0; i < 8; i++) {
        float s = bestScore[i];
        int   idx = bestIdx[i];
#pragma unroll
        for (int off = 8; off > 0; off >>= 1) {
            float so = __shfl_down_sync(0xffffffffu, s, off, 16);
            int   io = __shfl_down_sync(0xffffffffu, idx, off, 16);
            if (so > s || (so == s && io < idx)) { s = so; idx = io; }
        }
        if (tx == 0) best_s[ty + i * 8] = idx;
    }
    __syncthreads();

    // Epilogue: quantize rows (gather embed[best]) + segment-sum scatter
#pragma unroll
    for (int m = 0; m < 16; m++) {
        int flat = tid + m * 128;
        int r = flat >> 5, c = flat & 31;
        int best = best_s[r];
        float4 e4 = ((const float4*)(embed + (size_t)best * DIM))[c];
        ((float4*)(out + (rowBase + r) * DIM))[c] = e4;
        float4 xv = ((float4*)xs[r])[c];
        float* sp = g_sums + (size_t)best * DIM + c * 4;
        atomicAdd(sp + 0, xv.x);
        atomicAdd(sp + 1, xv.y);
        atomicAdd(sp + 2, xv.z);
        atomicAdd(sp + 3, xv.w);
    }
    if (tid < ROWS) {
        int best = best_s[tid];
        atomicAdd(&g_counts[best], 1.0f);
        out[indOff + rowBase + tid] = (float)best;
    }
}

// ---------------------------------------------------------------------------
// Kernel 2a: new_cluster_size + total + 1/smoothed_counts (1 block, 1024 thr)
// ---------------------------------------------------------------------------
__global__ void k_final1(const float* __restrict__ cs,
                         float* __restrict__ out,
                         long long ncsOff) {
    __shared__ float red[KCODES];
    int k = threadIdx.x;
    float ncs = cs[k] * DECAY_F + OMD_F * g_counts[k];
    out[ncsOff + k] = ncs;
    red[k] = ncs;
    __syncthreads();
    for (int s = KCODES / 2; s > 0; s >>= 1) {
        if (k < s) red[k] += red[k + s];
        __syncthreads();
    }
    float total    = red[0];
    float smoothed = (ncs + EPS_F) / (total + (float)KCODES * EPS_F);
    g_inv[k] = 1.0f / (smoothed * total);
}

// ---------------------------------------------------------------------------
// Kernel 2b: new_embed_avg + new_embed (131072 elems)
// ---------------------------------------------------------------------------
__global__ void k_final2(const float* __restrict__ ea,
                         float* __restrict__ out,
                         long long neaOff, long long neOff) {
    int i = blockIdx.x * blockDim.x + threadIdx.x;
    float nea = ea[i] * DECAY_F + OMD_F * g_sums[i];
    out[neaOff + i] = nea;
    out[neOff + i]  = nea * g_inv[i >> 7];
}

// ---------------------------------------------------------------------------
extern "C" void kernel_launch(void* const* d_in, const int* in_sizes, int n_in,
                              void* d_out, int out_size) {
    const float* x     = (const float*)d_in[0];
    const float* embed = (const float*)d_in[1];
    const float* cs    = (const float*)d_in[2];
    const float* ea    = (const float*)d_in[3];
    float* out = (float*)d_out;

    const long long N = in_sizes[0] / DIM;   // 65536 rows
    const long long indOff = N * DIM;
    const long long ncsOff = indOff + N;
    const long long neaOff = ncsOff + KCODES;
    const long long neOff  = neaOff + (long long)KCODES * DIM;

    static bool attr_set = false;
    const int SMEM_SZ = (ROWS + CT) * STRIDE4 * 16 + CT * 4 + ROWS * 4;
    if (!attr_set) {
        cudaFuncSetAttribute(k_main, cudaFuncAttributeMaxDynamicSharedMemorySize, SMEM_SZ);
        attr_set = true;
    }

    k_init<<<KCODES, DIM>>>(embed);
    k_main<<<(unsigned)(N / ROWS), 128, SMEM_SZ>>>(x, embed, out, indOff);
    k_final1<<<1, KCODES>>>(cs, out, ncsOff);
    k_final2<<<KCODES * DIM / 256, 256>>>(ea, out, neaOff, neOff);
}

// round 9
// speedup vs baseline: 1.0306x; 1.0020x over previous
#include <cuda_runtime.h>
#include <cstdint>

// Problem constants (shapes fixed by the reference: x [8,8192,128], embed [1024,128])
#define DIM     128
#define KCODES  1024
#define ROWS    64      // x rows per block
#define CT      128     // codes per tile (8 tiles)
#define STRIDE4 33      // padded row stride in float4 (132 floats)

static const float DECAY_F = 0.99f;
static const float OMD_F   = (float)(1.0 - 0.99);
static const float EPS_F   = 1e-5f;

// Scratch (no cudaMalloc allowed): device globals
__device__ float g_counts[KCODES];
__device__ float g_sums[KCODES * DIM];
__device__ float g_enorm[KCODES];
__device__ float g_inv[KCODES];

// packed fp32x2 FMA (Blackwell FFMA2): d = a*b + d on 2 packed f32
__device__ __forceinline__ void ffma2(unsigned long long& d,
                                      unsigned long long a,
                                      unsigned long long b) {
    asm("fma.rn.f32x2 %0, %1, %2, %0;" : "+l"(d) : "l"(a), "l"(b));
}

// ---------------------------------------------------------------------------
// Kernel 0: per-code squared norms + zero the accumulation scratch
// ---------------------------------------------------------------------------
__global__ void k_init(const float* __restrict__ embed) {
    int k = blockIdx.x;
    int t = threadIdx.x;
    float v = embed[k * DIM + t];
    float p = v * v;
#pragma unroll
    for (int off = 16; off > 0; off >>= 1)
        p += __shfl_down_sync(0xffffffffu, p, off);
    __shared__ float s[4];
    if ((t & 31) == 0) s[t >> 5] = p;
    __syncthreads();
    if (t == 0) {
        g_enorm[k]  = s[0] + s[1] + s[2] + s[3];
        g_counts[k] = 0.0f;
    }
    g_sums[(size_t)k * DIM + t] = 0.0f;
}

// ---------------------------------------------------------------------------
// Kernel 1: fused distance-GEMM + argmax + quantize gather + segment-sum
// grid = N/64 blocks x 128 threads (4 warps). 2 blocks/SM (102 KB smem each).
// Thread map: tx = tid&15 (code groups), ty = tid>>4 (row groups, 0..7)
//   rows  owned: ty + i*8,  i = 0..7   (64 rows/block)
//   codes owned: tx + j*16, j = 0..7   (128 codes/tile)
// 8x8 f32x2 microtile: 256 B smem -> 256 FMA per k4 step (1.0 B/FMA).
// ---------------------------------------------------------------------------
__global__ __launch_bounds__(128) void k_main(const float* __restrict__ x,
                                              const float* __restrict__ embed,
                                              float* __restrict__ out,
                                              long long indOff) {
    extern __shared__ unsigned char sm[];
    ulonglong2 (*xs)[STRIDE4] = (ulonglong2(*)[STRIDE4])sm;
    ulonglong2 (*es)[STRIDE4] = (ulonglong2(*)[STRIDE4])(sm + (size_t)ROWS * STRIDE4 * 16);
    float* enorm_s = (float*)(sm + (size_t)(ROWS + CT) * STRIDE4 * 16);
    int*   best_s  = (int*)(enorm_s + CT);

    const int tid = threadIdx.x;
    const int tx  = tid & 15;
    const int ty  = tid >> 4;
    const long long rowBase = (long long)blockIdx.x * ROWS;

    // Load x tile [64][128] (coalesced float4): 2048 float4 / 128 thr = 16 ea
    const float4* xg = (const float4*)(x + rowBase * DIM);
#pragma unroll
    for (int m = 0; m < 16; m++) {
        int flat = tid + m * 128;
        int r = flat >> 5, c = flat & 31;
        ((float4*)xs[r])[c] = xg[flat];
    }

    float bestScore[8];
    int   bestIdx[8];
#pragma unroll
    for (int i = 0; i < 8; i++) { bestScore[i] = -3.4e38f; bestIdx[i] = 0; }

    for (int tile = 0; tile < KCODES / CT; tile++) {
        __syncthreads();   // protect es/enorm_s reuse from previous iteration
        const float4* eg = (const float4*)(embed + (size_t)tile * CT * DIM);
#pragma unroll
        for (int m = 0; m < 32; m++) {
            int flat = tid + m * 128;
            int r = flat >> 5, c = flat & 31;
            ((float4*)es[r])[c] = eg[flat];
        }
        enorm_s[tid] = g_enorm[tile * CT + tid];
        __syncthreads();

        unsigned long long acc[8][8];
#pragma unroll
        for (int i = 0; i < 8; i++)
#pragma unroll
            for (int j = 0; j < 8; j++) acc[i][j] = 0ull;

#pragma unroll 1
        for (int k4 = 0; k4 < 32; k4++) {
            ulonglong2 a[8], b[8];
#pragma unroll
            for (int i = 0; i < 8; i++) a[i] = xs[ty + i * 8][k4];
#pragma unroll
            for (int j = 0; j < 8; j++) b[j] = es[tx + j * 16][k4];
#pragma unroll
            for (int i = 0; i < 8; i++)
#pragma unroll
                for (int j = 0; j < 8; j++) {
                    ffma2(acc[i][j], a[i].x, b[j].x);
                    ffma2(acc[i][j], a[i].y, b[j].y);
                }
        }

        // score = 2*dot - ||e||^2 ; argmax, first-index tie-break
#pragma unroll
        for (int i = 0; i < 8; i++)
#pragma unroll
            for (int j = 0; j < 8; j++) {
                unsigned long long v = acc[i][j];
                float lo  = __uint_as_float((unsigned)v);
                float hi  = __uint_as_float((unsigned)(v >> 32));
                float dot = lo + hi;
                int   code = tile * CT + j * 16 + tx;
                float sc   = 2.0f * dot - enorm_s[j * 16 + tx];
                if (sc > bestScore[i] || (sc == bestScore[i] && code < bestIdx[i])) {
                    bestScore[i] = sc;
                    bestIdx[i]   = code;
                }
            }
    }

    // Reduce over the 16 tx lanes (half-warp, width 16)
#pragma unroll
    for (int i = 0; i < 8; i++) {
        float s = bestScore[i];
        int   idx = bestIdx[i];
#pragma unroll
        for (int off = 8; off > 0; off >>= 1) {
            float so = __shfl_down_sync(0xffffffffu, s, off, 16);
            int   io = __shfl_down_sync(0xffffffffu, idx, off, 16);
            if (so > s || (so == s && io < idx)) { s = so; idx = io; }
        }
        if (tx == 0) best_s[ty + i * 8] = idx;
    }
    __syncthreads();

    // Epilogue: quantize rows (gather embed[best]) + segment-sum scatter
#pragma unroll
    for (int m = 0; m < 16; m++) {
        int flat = tid + m * 128;
        int r = flat >> 5, c = flat & 31;
        int best = best_s[r];
        float4 e4 = ((const float4*)(embed + (size_t)best * DIM))[c];
        ((float4*)(out + (rowBase + r) * DIM))[c] = e4;
        float4 xv = ((float4*)xs[r])[c];
        float* sp = g_sums + (size_t)best * DIM + c * 4;
        atomicAdd(sp + 0, xv.x);
        atomicAdd(sp + 1, xv.y);
        atomicAdd(sp + 2, xv.z);
        atomicAdd(sp + 3, xv.w);
    }
    if (tid < ROWS) {
        int best = best_s[tid];
        atomicAdd(&g_counts[best], 1.0f);
        out[indOff + rowBase + tid] = (float)best;
    }
}

// ---------------------------------------------------------------------------
// Kernel 2a: new_cluster_size + total + 1/smoothed_counts (1 block, 1024 thr)
// ---------------------------------------------------------------------------
__global__ void k_final1(const float* __restrict__ cs,
                         float* __restrict__ out,
                         long long ncsOff) {
    __shared__ float red[KCODES];
    int k = threadIdx.x;
    float ncs = cs[k] * DECAY_F + OMD_F * g_counts[k];
    out[ncsOff + k] = ncs;
    red[k] = ncs;
    __syncthreads();
    for (int s = KCODES / 2; s > 0; s >>= 1) {
        if (k < s) red[k] += red[k + s];
        __syncthreads();
    }
    float total    = red[0];
    float smoothed = (ncs + EPS_F) / (total + (float)KCODES * EPS_F);
    g_inv[k] = 1.0f / (smoothed * total);
}

// ---------------------------------------------------------------------------
// Kernel 2b: new_embed_avg + new_embed (131072 elems)
// ---------------------------------------------------------------------------
__global__ void k_final2(const float* __restrict__ ea,
                         float* __restrict__ out,
                         long long neaOff, long long neOff) {
    int i = blockIdx.x * blockDim.x + threadIdx.x;
    float nea = ea[i] * DECAY_F + OMD_F * g_sums[i];
    out[neaOff + i] = nea;
    out[neOff + i]  = nea * g_inv[i >> 7];
}

// ---------------------------------------------------------------------------
extern "C" void kernel_launch(void* const* d_in, const int* in_sizes, int n_in,
                              void* d_out, int out_size) {
    const float* x     = (const float*)d_in[0];
    const float* embed = (const float*)d_in[1];
    const float* cs    = (const float*)d_in[2];
    const float* ea    = (const float*)d_in[3];
    float* out = (float*)d_out;

    const long long N = in_sizes[0] / DIM;   // 65536 rows
    const long long indOff = N * DIM;
    const long long ncsOff = indOff + N;
    const long long neaOff = ncsOff + KCODES;
    const long long neOff  = neaOff + (long long)KCODES * DIM;

    static bool attr_set = false;
    const int SMEM_SZ = (ROWS + CT) * STRIDE4 * 16 + CT * 4 + ROWS * 4;
    if (!attr_set) {
        cudaFuncSetAttribute(k_main, cudaFuncAttributeMaxDynamicSharedMemorySize, SMEM_SZ);
        attr_set = true;
    }

    k_init<<<KCODES, DIM>>>(embed);
    k_main<<<(unsigned)(N / ROWS), 128, SMEM_SZ>>>(x, embed, out, indOff);
    k_final1<<<1, KCODES>>>(cs, out, ncsOff);
    k_final2<<<KCODES * DIM / 256, 256>>>(ea, out, neaOff, neOff);
}